// round 11
// baseline (speedup 1.0000x reference)
#include <cuda_runtime.h>
#include <cuda_bf16.h>
#include <cstdint>

#define NTH 256
#define STAGES 3

// W bf16 scratch: w0@0 (68352), w1@68352 (136704), w2@205056 (273408)
__device__ __nv_bfloat16 g_wb[478464];

__constant__ float g_anch[3][6] = {
    {10.f, 13.f, 16.f, 30.f, 33.f, 23.f},
    {30.f, 61.f, 62.f, 45.f, 59.f, 119.f},
    {116.f, 90.f, 156.f, 198.f, 373.f, 326.f}
};

__device__ __forceinline__ float sigm(float x) { return 1.f / (1.f + __expf(-x)); }

__device__ __forceinline__ void mma_bf16(float* c, const uint32_t* a, const uint32_t* b) {
    asm volatile(
        "mma.sync.aligned.m16n8k16.row.col.f32.bf16.bf16.f32 "
        "{%0,%1,%2,%3}, {%4,%5,%6,%7}, {%8,%9}, {%0,%1,%2,%3};"
        : "+f"(c[0]), "+f"(c[1]), "+f"(c[2]), "+f"(c[3])
        : "r"(a[0]), "r"(a[1]), "r"(a[2]), "r"(a[3]), "r"(b[0]), "r"(b[1]));
}
__device__ __forceinline__ void ldsm4(uint32_t* r, uint32_t addr) {
    asm volatile("ldmatrix.sync.aligned.m8n8.x4.shared.b16 {%0,%1,%2,%3}, [%4];"
                 : "=r"(r[0]), "=r"(r[1]), "=r"(r[2]), "=r"(r[3]) : "r"(addr));
}
__device__ __forceinline__ uint32_t cvt2(float lo, float hi) {
    uint32_t r;
    asm("cvt.rn.bf16x2.f32 %0, %1, %2;" : "=r"(r) : "f"(hi), "f"(lo));
    return r;
}
__device__ __forceinline__ void cp16(uint32_t saddr, const void* gptr, uint32_t sz) {
    asm volatile("cp.async.cg.shared.global [%0], [%1], 16, %2;"
                 :: "r"(saddr), "l"(gptr), "r"(sz) : "memory");
}
#define CP_COMMIT() asm volatile("cp.async.commit_group;" ::: "memory")
#define CP_WAIT()   asm volatile("cp.async.wait_group %0;" :: "n"(STAGES - 2) : "memory")

// CTA tile: 128 M x 64 N, K chunk 32.
// A: bf16 [128 m][40 halves] = 80 B/row. B stage: fp32 [32 k][68 f] = 272 B/row.
// Bt (per-chunk bf16 B tile): [64 n][40 halves] = 80 B/row.
#define A_ROW_B 80
#define B_ROW_F 68
#define BT_ROW_B 80
#define A_BYTES (128 * A_ROW_B)               // 10240
#define B_BYTES (32 * B_ROW_F * 4)            // 8704
#define STAGE_BYTES (A_BYTES + B_BYTES)       // 18944
#define BT_OFF (STAGES * STAGE_BYTES)         // 56832
#define BT_BYTES (64 * BT_ROW_B)              // 5120
#define DYN_BYTES (BT_OFF + BT_BYTES + 1088)  // 63040
#define PT_STRIDE 132                         // epilogue Pt[64][132] reuses stage area

__global__ void convert_w(const float* __restrict__ w0, const float* __restrict__ w1,
                          const float* __restrict__ w2)
{
    int i = blockIdx.x * 256 + threadIdx.x;
    if (i < 68352)        g_wb[i] = __float2bfloat16(w0[i]);
    else if (i < 205056)  g_wb[i] = __float2bfloat16(w1[i - 68352]);
    else if (i < 478464)  g_wb[i] = __float2bfloat16(w2[i - 205056]);
}

template<int C, int HW, int NX>
__device__ __forceinline__ void run_level(
    const float* __restrict__ X, const __nv_bfloat16* __restrict__ Wb,
    const float* __restrict__ Bias, float* __restrict__ Out,
    int bat, int mt, int nt, float stride_px, int lvl, int loff)
{
    extern __shared__ char sh[];
    float* sBias = (float*)(sh + BT_OFF + BT_BYTES);
    float* Pt = (float*)sh;
    const uint32_t shBase = (uint32_t)__cvta_generic_to_shared(sh);

    const int tid  = threadIdx.x;
    const int wid  = tid >> 5;
    const int lane = tid & 31;
    const int g    = lane >> 2;
    const int t4   = lane & 3;
    const int wm   = (wid & 3) * 32;     // 4 warps along M
    const int wn   = (wid >> 2) * 32;    // 2 warps along N
    const int m0   = mt * 128;
    const int n0   = nt * 64;
    const float* Xb = X + (size_t)bat * C * HW;

    for (int i = tid; i < 267; i += NTH) sBias[i] = Bias[i];

    // ---- cp.async loaders: threads 0-127 -> A (1 m-row), 128-255 -> B ----
    const bool isB = tid >= 128;
    const int t2 = tid & 127;
    const uint32_t aSz = ((m0 + t2) < 267) ? 16u : 0u;
    const __nv_bfloat16* aG = Wb + (size_t)((m0 + t2) < 267 ? (m0 + t2) : 0) * C;
    const uint32_t aS = shBase + t2 * A_ROW_B;
    const int bK = t2 >> 2;
    const int bSeg = (t2 & 3) * 16;
    const uint32_t bS = shBase + A_BYTES + (bK * B_ROW_F + bSeg) * 4;
    const float* bG = Xb + (size_t)bK * HW + n0 + bSeg;

    const int NCH = C / 32;
#pragma unroll
    for (int s = 0; s < STAGES - 1; ++s) {
        if (s < NCH) {
            if (!isB) {
#pragma unroll
                for (int q = 0; q < 4; ++q)
                    cp16(aS + s * STAGE_BYTES + q * 16, aG + (size_t)s * 32 + q * 8, aSz);
            } else {
#pragma unroll
                for (int q = 0; q < 4; ++q) {
                    const int gn = n0 + bSeg + q * 4;
                    cp16(bS + s * STAGE_BYTES + q * 16, bG + (size_t)s * 32 * HW + q * 4,
                         (gn < HW) ? 16u : 0u);
                }
            }
        }
        CP_COMMIT();
    }

    // fragment lane addresses (80 B rows, proven conflict-free)
    const uint32_t aLane = (uint32_t)((wm + (lane & 15)) * A_ROW_B + (lane >> 4) * 16);
    const uint32_t btLane = shBase + BT_OFF
        + (uint32_t)((wn + (lane & 7) + ((lane >> 4) << 3)) * BT_ROW_B + ((lane >> 3) & 1) * 16);

    // convert assignment: thread -> n row (cn), k octet (cq)
    const int cq = tid >> 6;          // 0..3
    const int cn = tid & 63;          // 0..63
    const uint32_t btSt = shBase + BT_OFF + cn * BT_ROW_B + cq * 16;

    float acc[2][4][4];
#pragma unroll
    for (int a = 0; a < 2; ++a)
#pragma unroll
        for (int b = 0; b < 4; ++b)
#pragma unroll
            for (int k = 0; k < 4; ++k) acc[a][b][k] = 0.f;

    int s = 0;
    for (int i = 0; i < NCH; ++i) {
        CP_WAIT();
        __syncthreads();

        // issue cp for chunk i+STAGES-1 into vacated slot
        const int ch = i + STAGES - 1;
        const int sn = (s + STAGES - 1 >= STAGES) ? s + STAGES - 1 - STAGES : s + STAGES - 1;
        if (ch < NCH) {
            if (!isB) {
#pragma unroll
                for (int q = 0; q < 4; ++q)
                    cp16(aS + sn * STAGE_BYTES + q * 16, aG + (size_t)ch * 32 + q * 8, aSz);
            } else {
#pragma unroll
                for (int q = 0; q < 4; ++q) {
                    const int gn = n0 + bSeg + q * 4;
                    cp16(bS + sn * STAGE_BYTES + q * 16, bG + (size_t)ch * 32 * HW + q * 4,
                         (gn < HW) ? 16u : 0u);
                }
            }
        }
        CP_COMMIT();

        // ---- cooperative convert: fp32 [k][n] stage -> bf16 Bt [n][k] ----
        {
            const float* Bst = (const float*)(sh + s * STAGE_BYTES + A_BYTES);
            float v[8];
#pragma unroll
            for (int j = 0; j < 8; ++j)
                v[j] = Bst[(size_t)(cq * 8 + j) * B_ROW_F + cn];
            uint4 pk;
            pk.x = cvt2(v[0], v[1]); pk.y = cvt2(v[2], v[3]);
            pk.z = cvt2(v[4], v[5]); pk.w = cvt2(v[6], v[7]);
            asm volatile("st.shared.v4.b32 [%0], {%1,%2,%3,%4};"
                         :: "r"(btSt), "r"(pk.x), "r"(pk.y), "r"(pk.z), "r"(pk.w) : "memory");
        }
        __syncthreads();

        const uint32_t stA = shBase + s * STAGE_BYTES + aLane;
#pragma unroll
        for (int kk = 0; kk < 2; ++kk) {
            uint32_t afr[2][4];
            ldsm4(afr[0], stA + kk * 32);
            ldsm4(afr[1], stA + 16 * A_ROW_B + kk * 32);

            uint32_t bfr[4][2];
            {
                uint32_t r[4];
                ldsm4(r, btLane + kk * 32);
                bfr[0][0] = r[0]; bfr[0][1] = r[1]; bfr[1][0] = r[2]; bfr[1][1] = r[3];
                ldsm4(r, btLane + 16 * BT_ROW_B + kk * 32);
                bfr[2][0] = r[0]; bfr[2][1] = r[1]; bfr[3][0] = r[2]; bfr[3][1] = r[3];
            }
#pragma unroll
            for (int ma = 0; ma < 2; ++ma)
#pragma unroll
                for (int na = 0; na < 4; ++na)
                    mma_bf16(acc[ma][na], afr[ma], bfr[na]);
        }
        s = (s + 1 == STAGES) ? 0 : s + 1;
    }

    // ---- epilogue phase 1: transpose acc -> Pt[n][m] ----
    __syncthreads();
#pragma unroll
    for (int ma = 0; ma < 2; ++ma)
#pragma unroll
        for (int h = 0; h < 2; ++h) {
            const int ml = wm + ma * 16 + g + h * 8;
#pragma unroll
            for (int na = 0; na < 4; ++na)
#pragma unroll
                for (int c = 0; c < 2; ++c) {
                    const int nl = wn + na * 8 + t4 * 2 + c;
                    Pt[nl * PT_STRIDE + ml] = acc[ma][na][h * 2 + c];
                }
        }
    __syncthreads();

    // ---- epilogue phase 2: coalesced decode+store ----
#pragma unroll
    for (int i = 0; i < 8; ++i) {
        const int nl = wid * 8 + i;
        const int n = n0 + nl;
        if (n >= HW) break;
        const float gx = (float)(n % NX);
        const float gy = (float)(n / NX);
        const size_t obase = ((size_t)bat * 25200 + loff + n) * 89;
#pragma unroll
        for (int p = 0; p < 4; ++p) {
            const int lm = p * 32 + lane;
            const int m = m0 + lm;
            if (m < 267) {
                const int ai = m / 89;
                const int e  = m - ai * 89;
                const float v = Pt[nl * PT_STRIDE + lm] + sBias[m];
                float res;
                if (e == 0)      res = (sigm(v) + gx) * stride_px;
                else if (e == 1) res = (sigm(v) + gy) * stride_px;
                else if (e < 4)  res = __expf(v) * g_anch[lvl][ai * 2 + (e - 2)];
                else             res = sigm(v);
                Out[obase + (size_t)ai * HW * 89 + e] = res;
            }
        }
    }
}

// N tiles (64-wide): L0 100, L1 25, L2 7 -> 132
__global__ void __launch_bounds__(NTH, 3)
detect_mma(const float* __restrict__ x0, const float* __restrict__ x1,
           const float* __restrict__ x2,
           const float* __restrict__ b0, const float* __restrict__ b1,
           const float* __restrict__ b2, float* __restrict__ out)
{
    const int xt  = blockIdx.x;
    const int mt  = blockIdx.y;
    const int bat = blockIdx.z;

    if (xt < 100)
        run_level<256, 6400, 80>(x0, g_wb, b0, out, bat, mt, xt, 8.f, 0, 0);
    else if (xt < 125)
        run_level<512, 1600, 40>(x1, g_wb + 68352, b1, out, bat, mt, xt - 100, 16.f, 1, 19200);
    else
        run_level<1024, 400, 20>(x2, g_wb + 205056, b2, out, bat, mt, xt - 125, 32.f, 2, 24000);
}

extern "C" void kernel_launch(void* const* d_in, const int* in_sizes, int n_in,
                              void* d_out, int out_size)
{
    const float *x0 = 0, *x1 = 0, *x2 = 0, *w0 = 0, *w1 = 0, *w2 = 0;
    const float* bs[3] = {0, 0, 0};
    int nb = 0;
    for (int i = 0; i < n_in; ++i) {
        const float* p = (const float*)d_in[i];
        switch (in_sizes[i]) {
            case 13107200: x0 = p; break;
            case 6553600:  x1 = p; break;
            case 3276800:  x2 = p; break;
            case 68352:    w0 = p; break;
            case 136704:   w1 = p; break;
            case 273408:   w2 = p; break;
            case 267:      if (nb < 3) bs[nb++] = p; break;
            default: break;
        }
    }

    convert_w<<<(478464 + 255) / 256, 256>>>(w0, w1, w2);

    cudaFuncSetAttribute(detect_mma, cudaFuncAttributeMaxDynamicSharedMemorySize, DYN_BYTES);
    dim3 grid(132, 3, 8);
    detect_mma<<<grid, NTH, DYN_BYTES>>>(x0, x1, x2, bs[0], bs[1], bs[2], (float*)d_out);
}

// round 13
// speedup vs baseline: 1.4384x; 1.4384x over previous
#include <cuda_runtime.h>
#include <cuda_bf16.h>
#include <cstdint>

#define NTH 256
#define STAGES 3

// W bf16 scratch: w0@0 (68352), w1@68352 (136704), w2@205056 (273408)
__device__ __nv_bfloat16 g_wb[478464];

__constant__ float g_anch[3][6] = {
    {10.f, 13.f, 16.f, 30.f, 33.f, 23.f},
    {30.f, 61.f, 62.f, 45.f, 59.f, 119.f},
    {116.f, 90.f, 156.f, 198.f, 373.f, 326.f}
};

__device__ __forceinline__ float sigm(float x) { return 1.f / (1.f + __expf(-x)); }

__device__ __forceinline__ void mma_bf16(float* c, const uint32_t* a, const uint32_t* b) {
    asm volatile(
        "mma.sync.aligned.m16n8k16.row.col.f32.bf16.bf16.f32 "
        "{%0,%1,%2,%3}, {%4,%5,%6,%7}, {%8,%9}, {%0,%1,%2,%3};"
        : "+f"(c[0]), "+f"(c[1]), "+f"(c[2]), "+f"(c[3])
        : "r"(a[0]), "r"(a[1]), "r"(a[2]), "r"(a[3]), "r"(b[0]), "r"(b[1]));
}
__device__ __forceinline__ void ldsm4(uint32_t* r, uint32_t addr) {
    asm volatile("ldmatrix.sync.aligned.m8n8.x4.shared.b16 {%0,%1,%2,%3}, [%4];"
                 : "=r"(r[0]), "=r"(r[1]), "=r"(r[2]), "=r"(r[3]) : "r"(addr));
}
__device__ __forceinline__ uint32_t cvt2(float lo, float hi) {
    uint32_t r;
    asm("cvt.rn.bf16x2.f32 %0, %1, %2;" : "=r"(r) : "f"(hi), "f"(lo));
    return r;
}
__device__ __forceinline__ void cp16(uint32_t saddr, const void* gptr, uint32_t sz) {
    asm volatile("cp.async.cg.shared.global [%0], [%1], 16, %2;"
                 :: "r"(saddr), "l"(gptr), "r"(sz) : "memory");
}
#define CP_COMMIT() asm volatile("cp.async.commit_group;" ::: "memory")
#define CP_WAIT()   asm volatile("cp.async.wait_group %0;" :: "n"(STAGES - 2) : "memory")

// CTA tile: 128 M x 64 N.  A: bf16 [128 m][40 halves] = 80 B/row (ldmatrix CF).
// B: fp32 [32 k][68 floats] (64 data + 4 pad) = 272 B/row (16B-aligned rows;
//    fragment LDS bank = 8*t4 + g + 8*na, all 32 distinct).
#define A_ROW_B 80
#define B_ROW_F 68
#define A_BYTES (128 * A_ROW_B)               // 10240
#define B_BYTES (32 * B_ROW_F * 4)            // 8704
#define STAGE_BYTES (A_BYTES + B_BYTES)       // 18944
#define DYN_BYTES (STAGES * STAGE_BYTES + 1072)  // 57904 -> 4 CTAs = 231.6 KB
#define PT_STRIDE 132

__global__ void convert_w(const float* __restrict__ w0, const float* __restrict__ w1,
                          const float* __restrict__ w2)
{
    int i = blockIdx.x * 256 + threadIdx.x;
    if (i < 68352)        g_wb[i] = __float2bfloat16(w0[i]);
    else if (i < 205056)  g_wb[i] = __float2bfloat16(w1[i - 68352]);
    else if (i < 478464)  g_wb[i] = __float2bfloat16(w2[i - 205056]);
}

template<int C, int HW, int NX>
__device__ __forceinline__ void run_level(
    const float* __restrict__ X, const __nv_bfloat16* __restrict__ Wb,
    const float* __restrict__ Bias, float* __restrict__ Out,
    int bat, int mt, int nt, float stride_px, int lvl, int loff)
{
    extern __shared__ char sh[];
    float* sBias = (float*)(sh + STAGES * STAGE_BYTES);
    float* Pt = (float*)sh;
    const uint32_t shBase = (uint32_t)__cvta_generic_to_shared(sh);

    const int tid  = threadIdx.x;
    const int wid  = tid >> 5;
    const int lane = tid & 31;
    const int g    = lane >> 2;
    const int t4   = lane & 3;
    const int wm   = (wid & 3) * 32;     // 4 warps along M
    const int wn   = (wid >> 2) * 32;    // 2 warps along N
    const int m0   = mt * 128;
    const int n0   = nt * 64;
    const float* Xb = X + (uint32_t)bat * (uint32_t)(C * HW);

    for (int i = tid; i < 267; i += NTH) sBias[i] = Bias[i];

    // ---- cp.async loaders: threads 0-127 -> A (1 m-row), 128-255 -> B ----
    const bool isB = tid >= 128;
    const int t2 = tid & 127;
    const uint32_t aSz = ((m0 + t2) < 267) ? 16u : 0u;
    const __nv_bfloat16* aG = Wb + (uint32_t)((m0 + t2) < 267 ? (m0 + t2) : 0) * (uint32_t)C;
    const uint32_t aS = shBase + t2 * A_ROW_B;
    const int bK = t2 >> 2;                 // k row 0..31
    const int bSeg = (t2 & 3) * 16;         // float offset 0/16/32/48
    const uint32_t bS = shBase + A_BYTES + (bK * B_ROW_F + bSeg) * 4;
    const float* bG = Xb + (uint32_t)bK * (uint32_t)HW + (uint32_t)(n0 + bSeg);

    const int NCH = C / 32;
#pragma unroll
    for (int s = 0; s < STAGES - 1; ++s) {
        if (s < NCH) {
            if (!isB) {
#pragma unroll
                for (int q = 0; q < 4; ++q)
                    cp16(aS + s * STAGE_BYTES + q * 16, aG + s * 32 + q * 8, aSz);
            } else {
#pragma unroll
                for (int q = 0; q < 4; ++q) {
                    const int gn = n0 + bSeg + q * 4;
                    cp16(bS + s * STAGE_BYTES + q * 16, bG + (uint32_t)(s * 32) * (uint32_t)HW + q * 4,
                         (gn < HW) ? 16u : 0u);
                }
            }
        }
        CP_COMMIT();
    }

    const uint32_t aLane = (uint32_t)((wm + (lane & 15)) * A_ROW_B + (lane >> 4) * 16);

    float acc[2][4][4];
#pragma unroll
    for (int a = 0; a < 2; ++a)
#pragma unroll
        for (int b = 0; b < 4; ++b)
#pragma unroll
            for (int k = 0; k < 4; ++k) acc[a][b][k] = 0.f;

    int s = 0;
    for (int i = 0; i < NCH; ++i) {
        CP_WAIT();
        __syncthreads();

        const uint32_t stA = shBase + s * STAGE_BYTES + aLane;
        const float* Bst = (const float*)(sh + s * STAGE_BYTES + A_BYTES);

        const int ch = i + STAGES - 1;
        const int sn = (s + STAGES - 1 >= STAGES) ? s + STAGES - 1 - STAGES : s + STAGES - 1;
        if (ch < NCH) {
            if (!isB) {
#pragma unroll
                for (int q = 0; q < 4; ++q)
                    cp16(aS + sn * STAGE_BYTES + q * 16, aG + ch * 32 + q * 8, aSz);
            } else {
#pragma unroll
                for (int q = 0; q < 4; ++q) {
                    const int gn = n0 + bSeg + q * 4;
                    cp16(bS + sn * STAGE_BYTES + q * 16, bG + (uint32_t)(ch * 32) * (uint32_t)HW + q * 4,
                         (gn < HW) ? 16u : 0u);
                }
            }
        }
        CP_COMMIT();

#pragma unroll
        for (int kk = 0; kk < 2; ++kk) {
            uint32_t afr[2][4];
#pragma unroll
            for (int ma = 0; ma < 2; ++ma)
                ldsm4(afr[ma], stA + ma * 16 * A_ROW_B + kk * 32);

            uint32_t bfr[4][2];
            const int kb = kk * 16;
#pragma unroll
            for (int na = 0; na < 4; ++na) {
                const int nc = wn + na * 8 + g;
                const float* p0 = Bst + (uint32_t)(kb + 2 * t4) * B_ROW_F + nc;
                bfr[na][0] = cvt2(p0[0], p0[B_ROW_F]);
                const float* p1 = p0 + 8 * B_ROW_F;
                bfr[na][1] = cvt2(p1[0], p1[B_ROW_F]);
            }
#pragma unroll
            for (int ma = 0; ma < 2; ++ma)
#pragma unroll
                for (int na = 0; na < 4; ++na)
                    mma_bf16(acc[ma][na], afr[ma], bfr[na]);
        }
        s = (s + 1 == STAGES) ? 0 : s + 1;
    }

    // ---- epilogue phase 1: transpose acc -> Pt[n][m] ----
    __syncthreads();
#pragma unroll
    for (int ma = 0; ma < 2; ++ma)
#pragma unroll
        for (int h = 0; h < 2; ++h) {
            const int ml = wm + ma * 16 + g + h * 8;
#pragma unroll
            for (int na = 0; na < 4; ++na)
#pragma unroll
                for (int c = 0; c < 2; ++c) {
                    const int nl = wn + na * 8 + t4 * 2 + c;
                    Pt[nl * PT_STRIDE + ml] = acc[ma][na][h * 2 + c];
                }
        }
    __syncthreads();

    // ---- epilogue phase 2: coalesced decode+store ----
#pragma unroll
    for (int i = 0; i < 8; ++i) {
        const int nl = wid * 8 + i;
        const int n = n0 + nl;
        if (n >= HW) break;
        const float gx = (float)(n % NX);
        const float gy = (float)(n / NX);
        const uint32_t obase = ((uint32_t)bat * 25200u + (uint32_t)(loff + n)) * 89u;
#pragma unroll
        for (int p = 0; p < 4; ++p) {
            const int lm = p * 32 + lane;
            const int m = m0 + lm;
            if (m < 267) {
                const int ai = m / 89;
                const int e  = m - ai * 89;
                const float v = Pt[nl * PT_STRIDE + lm] + sBias[m];
                float res;
                if (e == 0)      res = (sigm(v) + gx) * stride_px;
                else if (e == 1) res = (sigm(v) + gy) * stride_px;
                else if (e < 4)  res = __expf(v) * g_anch[lvl][ai * 2 + (e - 2)];
                else             res = sigm(v);
                Out[obase + (uint32_t)ai * (uint32_t)(HW * 89) + (uint32_t)e] = res;
            }
        }
    }
}

// N tiles (64-wide), LONG levels first: L2 (0-6), L1 (7-31), L0 (32-131)
__global__ void __launch_bounds__(NTH, 4)
detect_mma(const float* __restrict__ x0, const float* __restrict__ x1,
           const float* __restrict__ x2,
           const float* __restrict__ b0, const float* __restrict__ b1,
           const float* __restrict__ b2, float* __restrict__ out)
{
    const int xt  = blockIdx.x;
    const int mt  = blockIdx.y;
    const int bat = blockIdx.z;

    if (xt < 7)
        run_level<1024, 400, 20>(x2, g_wb + 205056, b2, out, bat, mt, xt, 32.f, 2, 24000);
    else if (xt < 32)
        run_level<512, 1600, 40>(x1, g_wb + 68352, b1, out, bat, mt, xt - 7, 16.f, 1, 19200);
    else
        run_level<256, 6400, 80>(x0, g_wb, b0, out, bat, mt, xt - 32, 8.f, 0, 0);
}

extern "C" void kernel_launch(void* const* d_in, const int* in_sizes, int n_in,
                              void* d_out, int out_size)
{
    const float *x0 = 0, *x1 = 0, *x2 = 0, *w0 = 0, *w1 = 0, *w2 = 0;
    const float* bs[3] = {0, 0, 0};
    int nb = 0;
    for (int i = 0; i < n_in; ++i) {
        const float* p = (const float*)d_in[i];
        switch (in_sizes[i]) {
            case 13107200: x0 = p; break;
            case 6553600:  x1 = p; break;
            case 3276800:  x2 = p; break;
            case 68352:    w0 = p; break;
            case 136704:   w1 = p; break;
            case 273408:   w2 = p; break;
            case 267:      if (nb < 3) bs[nb++] = p; break;
            default: break;
        }
    }

    convert_w<<<(478464 + 255) / 256, 256>>>(w0, w1, w2);

    cudaFuncSetAttribute(detect_mma, cudaFuncAttributeMaxDynamicSharedMemorySize, DYN_BYTES);
    dim3 grid(132, 3, 8);
    detect_mma<<<grid, NTH, DYN_BYTES>>>(x0, x1, x2, bs[0], bs[1], bs[2], (float*)d_out);
}

// round 14
// speedup vs baseline: 1.4553x; 1.0118x over previous
#include <cuda_runtime.h>
#include <cuda_bf16.h>
#include <cstdint>

#define NTH 256
#define SA 3                 // A (weights, L2-resident) pipeline depth
#define SB 5                 // B (X, DRAM) pipeline depth

// W bf16 scratch: w0@0 (68352), w1@68352 (136704), w2@205056 (273408)
__device__ __nv_bfloat16 g_wb[478464];

__constant__ float g_anch[3][6] = {
    {10.f, 13.f, 16.f, 30.f, 33.f, 23.f},
    {30.f, 61.f, 62.f, 45.f, 59.f, 119.f},
    {116.f, 90.f, 156.f, 198.f, 373.f, 326.f}
};

__device__ __forceinline__ float sigm(float x) { return 1.f / (1.f + __expf(-x)); }

__device__ __forceinline__ void mma_bf16(float* c, const uint32_t* a, const uint32_t* b) {
    asm volatile(
        "mma.sync.aligned.m16n8k16.row.col.f32.bf16.bf16.f32 "
        "{%0,%1,%2,%3}, {%4,%5,%6,%7}, {%8,%9}, {%0,%1,%2,%3};"
        : "+f"(c[0]), "+f"(c[1]), "+f"(c[2]), "+f"(c[3])
        : "r"(a[0]), "r"(a[1]), "r"(a[2]), "r"(a[3]), "r"(b[0]), "r"(b[1]));
}
__device__ __forceinline__ void ldsm4(uint32_t* r, uint32_t addr) {
    asm volatile("ldmatrix.sync.aligned.m8n8.x4.shared.b16 {%0,%1,%2,%3}, [%4];"
                 : "=r"(r[0]), "=r"(r[1]), "=r"(r[2]), "=r"(r[3]) : "r"(addr));
}
__device__ __forceinline__ uint32_t cvt2(float lo, float hi) {
    uint32_t r;
    asm("cvt.rn.bf16x2.f32 %0, %1, %2;" : "=r"(r) : "f"(hi), "f"(lo));
    return r;
}
__device__ __forceinline__ void cp16(uint32_t saddr, const void* gptr, uint32_t sz) {
    asm volatile("cp.async.cg.shared.global [%0], [%1], 16, %2;"
                 :: "r"(saddr), "l"(gptr), "r"(sz) : "memory");
}
#define CP_COMMIT()  asm volatile("cp.async.commit_group;" ::: "memory")
#define CP_WAIT_1()  asm volatile("cp.async.wait_group 1;" ::: "memory")
#define CP_WAIT_3()  asm volatile("cp.async.wait_group 3;" ::: "memory")

// CTA tile: 128 M x 64 N, K chunk 32.
// A: bf16 [128 m][40 halves] = 80 B/row (ldmatrix conflict-free).
// B: fp32 [32 k][68 floats] = 272 B/row (16B-aligned; frag bank = 8*t4+g+8*na, CF).
#define A_ROW_B 80
#define B_ROW_F 68
#define A_BYTES (128 * A_ROW_B)               // 10240
#define B_BYTES (32 * B_ROW_F * 4)            // 8704
#define B_OFF   (SA * A_BYTES)                // 30720
#define BIAS_OFF (B_OFF + SB * B_BYTES)       // 74240
#define DYN_BYTES (BIAS_OFF + 1072)           // 75312 -> 3 CTAs = 226 KB
#define PT_STRIDE 132

__global__ void convert_w(const float* __restrict__ w0, const float* __restrict__ w1,
                          const float* __restrict__ w2)
{
    int i = blockIdx.x * 256 + threadIdx.x;
    if (i < 68352)        g_wb[i] = __float2bfloat16(w0[i]);
    else if (i < 205056)  g_wb[i] = __float2bfloat16(w1[i - 68352]);
    else if (i < 478464)  g_wb[i] = __float2bfloat16(w2[i - 205056]);
}

template<int C, int HW, int NX>
__device__ __forceinline__ void run_level(
    const float* __restrict__ X, const __nv_bfloat16* __restrict__ Wb,
    const float* __restrict__ Bias, float* __restrict__ Out,
    int bat, int mt, int nt, float stride_px, int lvl, int loff)
{
    extern __shared__ char sh[];
    float* sBias = (float*)(sh + BIAS_OFF);
    float* Pt = (float*)sh;
    const uint32_t shBase = (uint32_t)__cvta_generic_to_shared(sh);

    const int tid  = threadIdx.x;
    const int wid  = tid >> 5;
    const int lane = tid & 31;
    const int g    = lane >> 2;
    const int t4   = lane & 3;
    const int wm   = (wid & 3) * 32;     // 4 warps along M
    const int wn   = (wid >> 2) * 32;    // 2 warps along N
    const int m0   = mt * 128;
    const int n0   = nt * 64;
    const float* Xb = X + (uint32_t)bat * (uint32_t)(C * HW);

    for (int i = tid; i < 267; i += NTH) sBias[i] = Bias[i];

    // ---- loaders: warps 0-3 (tid<128) -> A, warps 4-7 -> B ----
    const bool isB = tid >= 128;
    const int t2 = tid & 127;
    const uint32_t aSz = ((m0 + t2) < 267) ? 16u : 0u;
    const __nv_bfloat16* aG = Wb + (uint32_t)((m0 + t2) < 267 ? (m0 + t2) : 0) * (uint32_t)C;
    const uint32_t aS = shBase + t2 * A_ROW_B;
    const int bK = t2 >> 2;                 // k row 0..31
    const int bSeg = (t2 & 3) * 16;         // float offset 0/16/32/48
    const uint32_t bS = shBase + B_OFF + (bK * B_ROW_F + bSeg) * 4;
    const float* bG = Xb + (uint32_t)bK * (uint32_t)HW + (uint32_t)(n0 + bSeg);
    const uint32_t bSz = ((n0 + bSeg) < HW) ? 16u : 0u;   // 16-float seg fully in/out (HW%64==0)

    const int NCH = C / 32;   // >= 8 for all levels

    // ---- prologue: A issues chunks 0..1 (2 groups), B issues chunks 0..3 (4 groups) ----
    if (!isB) {
#pragma unroll
        for (int p = 0; p < SA - 1; ++p) {
#pragma unroll
            for (int q = 0; q < 4; ++q)
                cp16(aS + p * A_BYTES + q * 16, aG + p * 32 + q * 8, aSz);
            CP_COMMIT();
        }
    } else {
#pragma unroll
        for (int p = 0; p < SB - 1; ++p) {
#pragma unroll
            for (int q = 0; q < 4; ++q)
                cp16(bS + p * B_BYTES + q * 16, bG + (uint32_t)(p * 32) * (uint32_t)HW + q * 4, bSz);
            CP_COMMIT();
        }
    }

    const uint32_t aLane = (uint32_t)((wm + (lane & 15)) * A_ROW_B + (lane >> 4) * 16);

    float acc[2][4][4];
#pragma unroll
    for (int a = 0; a < 2; ++a)
#pragma unroll
        for (int b = 0; b < 4; ++b)
#pragma unroll
            for (int k = 0; k < 4; ++k) acc[a][b][k] = 0.f;

    int sa = 0, sb = 0, saN = SA - 1, sbN = SB - 1;
    for (int i = 0; i < NCH; ++i) {
        if (!isB) { CP_WAIT_1(); } else { CP_WAIT_3(); }
        __syncthreads();

        // issue next chunks into just-vacated slots
        if (!isB) {
            const int chA = i + SA - 1;
            if (chA < NCH) {
#pragma unroll
                for (int q = 0; q < 4; ++q)
                    cp16(aS + saN * A_BYTES + q * 16, aG + chA * 32 + q * 8, aSz);
            }
            CP_COMMIT();
        } else {
            const int chB = i + SB - 1;
            if (chB < NCH) {
#pragma unroll
                for (int q = 0; q < 4; ++q)
                    cp16(bS + sbN * B_BYTES + q * 16,
                         bG + (uint32_t)(chB * 32) * (uint32_t)HW + q * 4, bSz);
            }
            CP_COMMIT();
        }

        const uint32_t stA = shBase + sa * A_BYTES + aLane;
        const float* Bst = (const float*)(sh + B_OFF + sb * B_BYTES);

#pragma unroll
        for (int kk = 0; kk < 2; ++kk) {
            uint32_t afr[2][4];
#pragma unroll
            for (int ma = 0; ma < 2; ++ma)
                ldsm4(afr[ma], stA + ma * 16 * A_ROW_B + kk * 32);

            uint32_t bfr[4][2];
            const int kb = kk * 16;
#pragma unroll
            for (int na = 0; na < 4; ++na) {
                const int nc = wn + na * 8 + g;
                const float* p0 = Bst + (uint32_t)(kb + 2 * t4) * B_ROW_F + nc;
                bfr[na][0] = cvt2(p0[0], p0[B_ROW_F]);
                const float* p1 = p0 + 8 * B_ROW_F;
                bfr[na][1] = cvt2(p1[0], p1[B_ROW_F]);
            }
#pragma unroll
            for (int ma = 0; ma < 2; ++ma)
#pragma unroll
                for (int na = 0; na < 4; ++na)
                    mma_bf16(acc[ma][na], afr[ma], bfr[na]);
        }
        sa = (sa + 1 == SA) ? 0 : sa + 1;
        sb = (sb + 1 == SB) ? 0 : sb + 1;
        saN = (saN + 1 == SA) ? 0 : saN + 1;
        sbN = (sbN + 1 == SB) ? 0 : sbN + 1;
    }

    // ---- epilogue phase 1: transpose acc -> Pt[n][m] ----
    __syncthreads();
#pragma unroll
    for (int ma = 0; ma < 2; ++ma)
#pragma unroll
        for (int h = 0; h < 2; ++h) {
            const int ml = wm + ma * 16 + g + h * 8;
#pragma unroll
            for (int na = 0; na < 4; ++na)
#pragma unroll
                for (int c = 0; c < 2; ++c) {
                    const int nl = wn + na * 8 + t4 * 2 + c;
                    Pt[nl * PT_STRIDE + ml] = acc[ma][na][h * 2 + c];
                }
        }
    __syncthreads();

    // ---- epilogue phase 2: coalesced decode+store ----
#pragma unroll
    for (int i = 0; i < 8; ++i) {
        const int nl = wid * 8 + i;
        const int n = n0 + nl;
        if (n >= HW) break;
        const float gx = (float)(n % NX);
        const float gy = (float)(n / NX);
        const uint32_t obase = ((uint32_t)bat * 25200u + (uint32_t)(loff + n)) * 89u;
#pragma unroll
        for (int p = 0; p < 4; ++p) {
            const int lm = p * 32 + lane;
            const int m = m0 + lm;
            if (m < 267) {
                const int ai = m / 89;
                const int e  = m - ai * 89;
                const float v = Pt[nl * PT_STRIDE + lm] + sBias[m];
                float res;
                if (e == 0)      res = (sigm(v) + gx) * stride_px;
                else if (e == 1) res = (sigm(v) + gy) * stride_px;
                else if (e < 4)  res = __expf(v) * g_anch[lvl][ai * 2 + (e - 2)];
                else             res = sigm(v);
                Out[obase + (uint32_t)ai * (uint32_t)(HW * 89) + (uint32_t)e] = res;
            }
        }
    }
}

// N tiles (64-wide), LONG levels first: L2 (0-6), L1 (7-31), L0 (32-131)
__global__ void __launch_bounds__(NTH, 3)
detect_mma(const float* __restrict__ x0, const float* __restrict__ x1,
           const float* __restrict__ x2,
           const float* __restrict__ b0, const float* __restrict__ b1,
           const float* __restrict__ b2, float* __restrict__ out)
{
    const int xt  = blockIdx.x;
    const int mt  = blockIdx.y;
    const int bat = blockIdx.z;

    if (xt < 7)
        run_level<1024, 400, 20>(x2, g_wb + 205056, b2, out, bat, mt, xt, 32.f, 2, 24000);
    else if (xt < 32)
        run_level<512, 1600, 40>(x1, g_wb + 68352, b1, out, bat, mt, xt - 7, 16.f, 1, 19200);
    else
        run_level<256, 6400, 80>(x0, g_wb, b0, out, bat, mt, xt - 32, 8.f, 0, 0);
}

extern "C" void kernel_launch(void* const* d_in, const int* in_sizes, int n_in,
                              void* d_out, int out_size)
{
    const float *x0 = 0, *x1 = 0, *x2 = 0, *w0 = 0, *w1 = 0, *w2 = 0;
    const float* bs[3] = {0, 0, 0};
    int nb = 0;
    for (int i = 0; i < n_in; ++i) {
        const float* p = (const float*)d_in[i];
        switch (in_sizes[i]) {
            case 13107200: x0 = p; break;
            case 6553600:  x1 = p; break;
            case 3276800:  x2 = p; break;
            case 68352:    w0 = p; break;
            case 136704:   w1 = p; break;
            case 273408:   w2 = p; break;
            case 267:      if (nb < 3) bs[nb++] = p; break;
            default: break;
        }
    }

    convert_w<<<(478464 + 255) / 256, 256>>>(w0, w1, w2);

    cudaFuncSetAttribute(detect_mma, cudaFuncAttributeMaxDynamicSharedMemorySize, DYN_BYTES);
    dim3 grid(132, 3, 8);
    detect_mma<<<grid, NTH, DYN_BYTES>>>(x0, x1, x2, bs[0], bs[1], bs[2], (float*)d_out);
}

// round 15
// speedup vs baseline: 1.7435x; 1.1980x over previous
#include <cuda_runtime.h>
#include <cuda_bf16.h>
#include <cstdint>

#define NTH 256
#define STAGES 3

// W bf16 scratch: w0@0 (68352), w1@68352 (136704), w2@205056 (273408)
__device__ __nv_bfloat16 g_wb[478464];

__constant__ float g_anch[3][6] = {
    {10.f, 13.f, 16.f, 30.f, 33.f, 23.f},
    {30.f, 61.f, 62.f, 45.f, 59.f, 119.f},
    {116.f, 90.f, 156.f, 198.f, 373.f, 326.f}
};

__device__ __forceinline__ void mma_bf16(float* c, const uint32_t* a, const uint32_t* b) {
    asm volatile(
        "mma.sync.aligned.m16n8k16.row.col.f32.bf16.bf16.f32 "
        "{%0,%1,%2,%3}, {%4,%5,%6,%7}, {%8,%9}, {%0,%1,%2,%3};"
        : "+f"(c[0]), "+f"(c[1]), "+f"(c[2]), "+f"(c[3])
        : "r"(a[0]), "r"(a[1]), "r"(a[2]), "r"(a[3]), "r"(b[0]), "r"(b[1]));
}
__device__ __forceinline__ void ldsm4(uint32_t* r, uint32_t addr) {
    asm volatile("ldmatrix.sync.aligned.m8n8.x4.shared.b16 {%0,%1,%2,%3}, [%4];"
                 : "=r"(r[0]), "=r"(r[1]), "=r"(r[2]), "=r"(r[3]) : "r"(addr));
}
__device__ __forceinline__ uint32_t cvt2(float lo, float hi) {
    uint32_t r;
    asm("cvt.rn.bf16x2.f32 %0, %1, %2;" : "=r"(r) : "f"(hi), "f"(lo));
    return r;
}
__device__ __forceinline__ void cp16(uint32_t saddr, const void* gptr, uint32_t sz) {
    asm volatile("cp.async.cg.shared.global [%0], [%1], 16, %2;"
                 :: "r"(saddr), "l"(gptr), "r"(sz) : "memory");
}
#define CP_COMMIT() asm volatile("cp.async.commit_group;" ::: "memory")
#define CP_WAIT()   asm volatile("cp.async.wait_group %0;" :: "n"(STAGES - 2) : "memory")

// CTA tile: 128 M x 64 N.  A: bf16 [128 m][40 halves] = 80 B/row (ldmatrix CF).
// B: fp32 [32 k][68 floats] = 272 B/row (16B-aligned; frag bank = 8*t4+g+8*na, CF).
#define A_ROW_B 80
#define B_ROW_F 68
#define A_BYTES (128 * A_ROW_B)               // 10240
#define B_BYTES (32 * B_ROW_F * 4)            // 8704
#define STAGE_BYTES (A_BYTES + B_BYTES)       // 18944
#define DYN_BYTES (STAGES * STAGE_BYTES + 1072)  // 57904 -> 3 CTAs
#define PT_STRIDE 68                          // Pt[128 m][68 n-floats] = 34816 B (reuse)

__global__ void convert_w(const float* __restrict__ w0, const float* __restrict__ w1,
                          const float* __restrict__ w2)
{
    int i = blockIdx.x * 256 + threadIdx.x;
    if (i < 68352)        g_wb[i] = __float2bfloat16(w0[i]);
    else if (i < 205056)  g_wb[i] = __float2bfloat16(w1[i - 68352]);
    else if (i < 478464)  g_wb[i] = __float2bfloat16(w2[i - 205056]);
}

template<int C, int HW, int NX>
__device__ __forceinline__ void run_level(
    const float* __restrict__ X, const __nv_bfloat16* __restrict__ Wb,
    const float* __restrict__ Bias, float* __restrict__ Out,
    int bat, int mt, int nt, float stride_px, int lvl, int loff)
{
    extern __shared__ char sh[];
    float* sBias = (float*)(sh + STAGES * STAGE_BYTES);
    float* Pt = (float*)sh;
    const uint32_t shBase = (uint32_t)__cvta_generic_to_shared(sh);

    const int tid  = threadIdx.x;
    const int wid  = tid >> 5;
    const int lane = tid & 31;
    const int g    = lane >> 2;
    const int t4   = lane & 3;
    const int wm   = (wid & 3) * 32;     // 4 warps along M
    const int wn   = (wid >> 2) * 32;    // 2 warps along N
    const int m0   = mt * 128;
    const int n0   = nt * 64;
    const float* Xb = X + (uint32_t)bat * (uint32_t)(C * HW);

    for (int i = tid; i < 267; i += NTH) sBias[i] = Bias[i];

    // ---- cp.async loaders: threads 0-127 -> A (1 m-row), 128-255 -> B ----
    const bool isB = tid >= 128;
    const int t2 = tid & 127;
    const uint32_t aSz = ((m0 + t2) < 267) ? 16u : 0u;
    const __nv_bfloat16* aG = Wb + (uint32_t)((m0 + t2) < 267 ? (m0 + t2) : 0) * (uint32_t)C;
    const uint32_t aS = shBase + t2 * A_ROW_B;
    const int bK = t2 >> 2;                 // k row 0..31
    const int bSeg = (t2 & 3) * 16;         // float offset 0/16/32/48
    const uint32_t bS = shBase + A_BYTES + (bK * B_ROW_F + bSeg) * 4;
    const float* bG = Xb + (uint32_t)bK * (uint32_t)HW + (uint32_t)(n0 + bSeg);
    const uint32_t bSz = ((n0 + bSeg) < HW) ? 16u : 0u;

    const int NCH = C / 32;
#pragma unroll
    for (int s = 0; s < STAGES - 1; ++s) {
        if (!isB) {
#pragma unroll
            for (int q = 0; q < 4; ++q)
                cp16(aS + s * STAGE_BYTES + q * 16, aG + s * 32 + q * 8, aSz);
        } else {
#pragma unroll
            for (int q = 0; q < 4; ++q)
                cp16(bS + s * STAGE_BYTES + q * 16,
                     bG + (uint32_t)(s * 32) * (uint32_t)HW + q * 4, bSz);
        }
        CP_COMMIT();
    }

    const uint32_t aLane = (uint32_t)((wm + (lane & 15)) * A_ROW_B + (lane >> 4) * 16);

    float acc[2][4][4];
#pragma unroll
    for (int a = 0; a < 2; ++a)
#pragma unroll
        for (int b = 0; b < 4; ++b)
#pragma unroll
            for (int k = 0; k < 4; ++k) acc[a][b][k] = 0.f;

    int s = 0;
    for (int i = 0; i < NCH; ++i) {
        CP_WAIT();
        __syncthreads();

        const uint32_t stA = shBase + s * STAGE_BYTES + aLane;
        const float* Bst = (const float*)(sh + s * STAGE_BYTES + A_BYTES);

        const int ch = i + STAGES - 1;
        const int sn = (s + STAGES - 1 >= STAGES) ? s + STAGES - 1 - STAGES : s + STAGES - 1;
        if (ch < NCH) {
            if (!isB) {
#pragma unroll
                for (int q = 0; q < 4; ++q)
                    cp16(aS + sn * STAGE_BYTES + q * 16, aG + ch * 32 + q * 8, aSz);
            } else {
#pragma unroll
                for (int q = 0; q < 4; ++q)
                    cp16(bS + sn * STAGE_BYTES + q * 16,
                         bG + (uint32_t)(ch * 32) * (uint32_t)HW + q * 4, bSz);
            }
        }
        CP_COMMIT();

#pragma unroll
        for (int kk = 0; kk < 2; ++kk) {
            uint32_t afr[2][4];
#pragma unroll
            for (int ma = 0; ma < 2; ++ma)
                ldsm4(afr[ma], stA + ma * 16 * A_ROW_B + kk * 32);

            uint32_t bfr[4][2];
            const int kb = kk * 16;
#pragma unroll
            for (int na = 0; na < 4; ++na) {
                const int nc = wn + na * 8 + g;
                const float* p0 = Bst + (uint32_t)(kb + 2 * t4) * B_ROW_F + nc;
                bfr[na][0] = cvt2(p0[0], p0[B_ROW_F]);
                const float* p1 = p0 + 8 * B_ROW_F;
                bfr[na][1] = cvt2(p1[0], p1[B_ROW_F]);
            }
#pragma unroll
            for (int ma = 0; ma < 2; ++ma)
#pragma unroll
                for (int na = 0; na < 4; ++na)
                    mma_bf16(acc[ma][na], afr[ma], bfr[na]);
        }
        s = (s + 1 == STAGES) ? 0 : s + 1;
    }

    // ---- epilogue phase 1: acc -> Pt[m][n] (STS.64 pairs) ----
    __syncthreads();
#pragma unroll
    for (int ma = 0; ma < 2; ++ma)
#pragma unroll
        for (int h = 0; h < 2; ++h) {
            const int ml = wm + ma * 16 + g + h * 8;
#pragma unroll
            for (int na = 0; na < 4; ++na) {
                const int nl = wn + na * 8 + t4 * 2;
                *(float2*)&Pt[ml * PT_STRIDE + nl] =
                    make_float2(acc[ma][na][h * 2], acc[ma][na][h * 2 + 1]);
            }
        }
    __syncthreads();

    // ---- epilogue phase 2: hoisted decode, coalesced store ----
    const float L2E = 1.44269504f;
    float gxs[8], gys[8];
#pragma unroll
    for (int i = 0; i < 8; ++i) {
        const int n = n0 + wid * 8 + i;
        gxs[i] = (float)(n % NX) * stride_px;
        gys[i] = (float)(n / NX) * stride_px;
    }
    const uint32_t obW = ((uint32_t)bat * 25200u + (uint32_t)(loff + n0 + wid * 8)) * 89u;

#pragma unroll
    for (int p = 0; p < 4; ++p) {
        const int lm = p * 32 + lane;
        const int m = m0 + lm;
        const bool vld = m < 267;
        const int mi = vld ? m : 266;
        const int ai = mi / 89;
        const int e  = mi - ai * 89;
        const float bv = sBias[mi];
        const uint32_t off = (uint32_t)ai * (uint32_t)(HW * 89) + (uint32_t)e;
        const bool pex = (e == 2) || (e == 3);
        const float anc = pex ? g_anch[lvl][ai * 2 + (e == 3 ? 1 : 0)] : 0.f;
        const float sgn = pex ? L2E : -L2E;
        const float sc  = (e < 2) ? stride_px : 1.f;
        const float w0  = (e == 0) ? 1.f : 0.f;
        const float w1  = (e == 1) ? 1.f : 0.f;

        float pv[8];
        *(float4*)pv       = *(const float4*)&Pt[lm * PT_STRIDE + wid * 8];
        *(float4*)(pv + 4) = *(const float4*)&Pt[lm * PT_STRIDE + wid * 8 + 4];

#pragma unroll
        for (int i = 0; i < 8; ++i) {
            if (HW % 64 != 0) { if (n0 + wid * 8 + i >= HW) break; }
            const float v = pv[i] + bv;
            float u;
            asm("ex2.approx.ftz.f32 %0, %1;" : "=f"(u) : "f"(v * sgn));
            float sden;
            asm("rcp.approx.ftz.f32 %0, %1;" : "=f"(sden) : "f"(1.f + u));
            const float gadd = fmaf(w0, gxs[i], w1 * gys[i]);
            const float rsig = fmaf(sden, sc, gadd);
            const float res = pex ? u * anc : rsig;
            if (vld) Out[obW + (uint32_t)i * 89u + off] = res;
        }
    }
}

// N tiles (64-wide), LONG levels first: L2 (0-6), L1 (7-31), L0 (32-131)
__global__ void __launch_bounds__(NTH, 3)
detect_mma(const float* __restrict__ x0, const float* __restrict__ x1,
           const float* __restrict__ x2,
           const float* __restrict__ b0, const float* __restrict__ b1,
           const float* __restrict__ b2, float* __restrict__ out)
{
    const int xt  = blockIdx.x;
    const int mt  = blockIdx.y;
    const int bat = blockIdx.z;

    if (xt < 7)
        run_level<1024, 400, 20>(x2, g_wb + 205056, b2, out, bat, mt, xt, 32.f, 2, 24000);
    else if (xt < 32)
        run_level<512, 1600, 40>(x1, g_wb + 68352, b1, out, bat, mt, xt - 7, 16.f, 1, 19200);
    else
        run_level<256, 6400, 80>(x0, g_wb, b0, out, bat, mt, xt - 32, 8.f, 0, 0);
}

extern "C" void kernel_launch(void* const* d_in, const int* in_sizes, int n_in,
                              void* d_out, int out_size)
{
    const float *x0 = 0, *x1 = 0, *x2 = 0, *w0 = 0, *w1 = 0, *w2 = 0;
    const float* bs[3] = {0, 0, 0};
    int nb = 0;
    for (int i = 0; i < n_in; ++i) {
        const float* p = (const float*)d_in[i];
        switch (in_sizes[i]) {
            case 13107200: x0 = p; break;
            case 6553600:  x1 = p; break;
            case 3276800:  x2 = p; break;
            case 68352:    w0 = p; break;
            case 136704:   w1 = p; break;
            case 273408:   w2 = p; break;
            case 267:      if (nb < 3) bs[nb++] = p; break;
            default: break;
        }
    }

    convert_w<<<(478464 + 255) / 256, 256>>>(w0, w1, w2);

    cudaFuncSetAttribute(detect_mma, cudaFuncAttributeMaxDynamicSharedMemorySize, DYN_BYTES);
    dim3 grid(132, 3, 8);
    detect_mma<<<grid, NTH, DYN_BYTES>>>(x0, x1, x2, bs[0], bs[1], bs[2], (float*)d_out);
}